// round 2
// baseline (speedup 1.0000x reference)
#include <cuda_runtime.h>
#include <math.h>

// ---------------- problem constants ----------------
#define NHEADS 8
#define NPOINTS 8
#define NDZ 4
#define DMODEL 256
#define NCAM 6
#define NQ 4096
#define FH 56
#define FW 100
#define FHW (FH*FW)          // 5600
#define BNQ (NCAM*NQ)        // 24576 rows of (cam,query)
#define MV  (NCAM*FHW)       // 33600 rows of (cam,pixel)
#define MVP 33664            // MV padded to multiple of 128 for GEMM tiling

// ---------------- scratch (device globals; no allocation) ----------------
// Padded region of g_src ([MV..MVP) rows) is never written: .bss zero-init,
// so the padded GEMM output rows are well-defined and never read.
__device__ float g_qp   [BNQ*DMODEL];          // queries + pos_emb
__device__ float g_src  [MVP*DMODEL];          // features transposed + embeddings
__device__ float g_value[MVP*DMODEL];          // value projection
__device__ float g_off  [BNQ*NHEADS*NPOINTS*2];// raw sampling offsets (pixels)
__device__ float g_attn [BNQ*NHEADS*NPOINTS];  // attention logits
__device__ float g_out  [BNQ*DMODEL];          // sampled+weighted output
__device__ float g_qa   [BNQ*DMODEL];          // attn-out projection
__device__ float g_slots[NQ*DMODEL];           // masked camera-combine
__device__ float g_valid[NCAM*NQ];             // per (cam,q) validity

// ---------------- fp32 GEMM: C[M,N] = A[M,K] @ B[N,K]^T + bias ----------------
// BM=128, BN=64, BK=16, 256 threads, 8x4 microtile, double-buffered smem with
// register prefetch. Call sites guarantee M%128==0, N%64==0, K%16==0.
template<int M, int N, int K>
__device__ __forceinline__ void sgemm_bt(const float* __restrict__ A,
                                         const float* __restrict__ B,
                                         const float* __restrict__ bias,
                                         float* __restrict__ C)
{
    constexpr int BM = 128, BN = 64, BK = 16;
    __shared__ float sA[2][BK][BM];
    __shared__ float sB[2][BK][BN];

    const int t  = threadIdx.x;          // 0..255
    const int tx = t & 15;               // compute: cols tx*4 .. +4
    const int ty = t >> 4;               // compute: rows ty*8 .. +8
    const int m0 = blockIdx.y * BM;
    const int n0 = blockIdx.x * BN;

    // load maps
    const int alr = t >> 1;              // A tile row 0..127
    const int alk = (t & 1) * 8;         // A k offset 0 or 8 (two float4)
    const int blr = t >> 2;              // B tile row 0..63
    const int blk = (t & 3) * 4;         // B k offset (one float4)

    const float* Ap = A + (size_t)(m0 + alr) * K + alk;
    const float* Bp = B + (size_t)(n0 + blr) * K + blk;

    // prefetch first tile into registers
    float4 a0 = *(const float4*)(Ap);
    float4 a1 = *(const float4*)(Ap + 4);
    float4 b0 = *(const float4*)(Bp);

    float acc[8][4] = {};
    int buf = 0;

    for (int k0 = 0; k0 < K; k0 += BK) {
        // stage registers -> smem[buf] (transposed A)
        sA[buf][alk+0][alr] = a0.x; sA[buf][alk+1][alr] = a0.y;
        sA[buf][alk+2][alr] = a0.z; sA[buf][alk+3][alr] = a0.w;
        sA[buf][alk+4][alr] = a1.x; sA[buf][alk+5][alr] = a1.y;
        sA[buf][alk+6][alr] = a1.z; sA[buf][alk+7][alr] = a1.w;
        sB[buf][blk+0][blr] = b0.x; sB[buf][blk+1][blr] = b0.y;
        sB[buf][blk+2][blr] = b0.z; sB[buf][blk+3][blr] = b0.w;
        __syncthreads();

        // prefetch next tile while computing this one
        if (k0 + BK < K) {
            a0 = *(const float4*)(Ap + k0 + BK);
            a1 = *(const float4*)(Ap + k0 + BK + 4);
            b0 = *(const float4*)(Bp + k0 + BK);
        }

        #pragma unroll
        for (int kk = 0; kk < BK; kk++) {
            float4 ra0 = *(const float4*)(&sA[buf][kk][ty * 8]);
            float4 ra1 = *(const float4*)(&sA[buf][kk][ty * 8 + 4]);
            float4 rb  = *(const float4*)(&sB[buf][kk][tx * 4]);
            float av[8] = {ra0.x, ra0.y, ra0.z, ra0.w, ra1.x, ra1.y, ra1.z, ra1.w};
            float bv[4] = {rb.x, rb.y, rb.z, rb.w};
            #pragma unroll
            for (int i = 0; i < 8; i++)
                #pragma unroll
                for (int j = 0; j < 4; j++)
                    acc[i][j] += av[i] * bv[j];
        }
        buf ^= 1;
    }

    float4 bb = *(const float4*)(bias + n0 + tx * 4);
    #pragma unroll
    for (int i = 0; i < 8; i++) {
        float4 o;
        o.x = acc[i][0] + bb.x;
        o.y = acc[i][1] + bb.y;
        o.z = acc[i][2] + bb.z;
        o.w = acc[i][3] + bb.w;
        *(float4*)(C + (size_t)(m0 + ty * 8 + i) * N + n0 + tx * 4) = o;
    }
}

// GEMM wrapper kernels (scratch referenced directly, weights via params)
__global__ __launch_bounds__(256) void k_gemm_value(const float* W, const float* b) {
    sgemm_bt<MVP, DMODEL, DMODEL>(g_src, W, b, g_value);
}
__global__ __launch_bounds__(256) void k_gemm_off(const float* W, const float* b) {
    sgemm_bt<BNQ, NHEADS*NPOINTS*2, DMODEL>(g_qp, W, b, g_off);
}
__global__ __launch_bounds__(256) void k_gemm_attn(const float* W, const float* b) {
    sgemm_bt<BNQ, NHEADS*NPOINTS, DMODEL>(g_qp, W, b, g_attn);
}
__global__ __launch_bounds__(256) void k_gemm_attnout(const float* W, const float* b) {
    sgemm_bt<BNQ, DMODEL, DMODEL>(g_out, W, b, g_qa);
}
__global__ __launch_bounds__(256) void k_gemm_final(const float* W, const float* b, float* C) {
    sgemm_bt<NQ, DMODEL, DMODEL>(g_slots, W, b, C);
}

// ---------------- qp = queries + pos_emb (pos broadcast over cameras) ----------------
__global__ void k_qp(const float* __restrict__ qr, const float* __restrict__ pe) {
    int i = blockIdx.x * blockDim.x + threadIdx.x;
    if (i < BNQ * DMODEL)
        g_qp[i] = qr[i] + pe[i & (NQ * DMODEL - 1)];   // NQ*DMODEL = 2^20
}

// ---------------- src: transpose features (cam,c,pix)->(cam,pix,c) + lvl/cam emb ----------------
__global__ void k_src(const float* __restrict__ feat,
                      const float* __restrict__ lvl,
                      const float* __restrict__ came)
{
    __shared__ float s[32][33];
    const int cam = blockIdx.z;
    const int p0  = blockIdx.x * 32;
    const int c0  = blockIdx.y * 32;
    const int tx  = threadIdx.x;     // 32
    const int ty  = threadIdx.y;     // 8
    #pragma unroll
    for (int j = 0; j < 4; j++) {
        int c = c0 + ty + j * 8;
        s[ty + j * 8][tx] = feat[((size_t)cam * DMODEL + c) * FHW + p0 + tx];
    }
    __syncthreads();
    #pragma unroll
    for (int j = 0; j < 4; j++) {
        int p = p0 + ty + j * 8;
        int c = c0 + tx;
        g_src[((size_t)cam * FHW + p) * DMODEL + c] = s[tx][ty + j * 8] + lvl[c] + came[cam * DMODEL + c];
    }
}

// ---------------- validity: any over z of bev_mask[0,cam,q,z,0] ----------------
// Works whether the bool mask was materialized as int32 (0/1) or float32 (0.0/1.0):
// the bit pattern of "false/0" is all-zero either way.
__global__ void k_valid(const int* __restrict__ mask) {
    int i = blockIdx.x * blockDim.x + threadIdx.x;
    if (i >= NCAM * NQ) return;
    const int* mp = mask + (size_t)i * (NDZ * 2);
    g_valid[i] = (mp[0] | mp[2] | mp[4] | mp[6]) ? 1.0f : 0.0f;
}

// ---------------- sampling: softmax + bilinear gather + weighted sum ----------------
// One warp per (cam*q row, head); lane = channel within head (dh=32).
__global__ __launch_bounds__(256) void k_sample(const float* __restrict__ refpts) {
    const int gwarp = (blockIdx.x * blockDim.x + threadIdx.x) >> 5;
    const int lane  = threadIdx.x & 31;
    const int h = gwarp & 7;
    const int m = gwarp >> 3;              // 0..BNQ-1
    if (m >= BNQ) return;
    const int cam = m >> 12;               // m / NQ

    // softmax over 8 points for this head (redundant across lanes; broadcast loads)
    const float* lg = g_attn + (size_t)m * (NHEADS * NPOINTS) + h * NPOINTS;
    float l[NPOINTS];
    float mx = -1e30f;
    #pragma unroll
    for (int p = 0; p < NPOINTS; p++) { l[p] = lg[p]; mx = fmaxf(mx, l[p]); }
    float ssum = 0.0f;
    #pragma unroll
    for (int p = 0; p < NPOINTS; p++) { l[p] = __expf(l[p] - mx); ssum += l[p]; }
    const float inv = 1.0f / ssum;

    const float* offp = g_off + (size_t)m * (NHEADS * NPOINTS * 2) + h * (NPOINTS * 2);
    const float* rp   = refpts + (size_t)m * (NDZ * 2);
    const float* vb   = g_value + ((size_t)cam * FHW) * DMODEL + h * 32 + lane;

    float acc = 0.0f;
    #pragma unroll
    for (int p = 0; p < NPOINTS; p++) {
        const float wq = l[p] * inv;
        const int z = p & 3;
        // loc = ref + off_raw/(W,H); x = loc_x*W - 0.5  ==  ref_x*W + off_raw_x - 0.5
        const float x = rp[z * 2 + 0] * (float)FW + offp[p * 2 + 0] - 0.5f;
        const float y = rp[z * 2 + 1] * (float)FH + offp[p * 2 + 1] - 0.5f;
        const float x0f = floorf(x), y0f = floorf(y);
        const int x0 = (int)x0f, y0 = (int)y0f;
        const int x1 = x0 + 1,  y1 = y0 + 1;
        const float wx1 = x - x0f, wx0 = 1.0f - wx1;
        const float wy1 = y - y0f, wy0 = 1.0f - wy1;
        const bool vx0 = (x0 >= 0) & (x0 < FW);
        const bool vx1 = (x1 >= 0) & (x1 < FW);
        const bool vy0 = (y0 >= 0) & (y0 < FH);
        const bool vy1 = (y1 >= 0) & (y1 < FH);
        float v00 = (vx0 & vy0) ? vb[(size_t)(y0 * FW + x0) * DMODEL] : 0.0f;
        float v10 = (vx1 & vy0) ? vb[(size_t)(y0 * FW + x1) * DMODEL] : 0.0f;
        float v01 = (vx0 & vy1) ? vb[(size_t)(y1 * FW + x0) * DMODEL] : 0.0f;
        float v11 = (vx1 & vy1) ? vb[(size_t)(y1 * FW + x1) * DMODEL] : 0.0f;
        acc += wq * (wx0 * wy0 * v00 + wx1 * wy0 * v10 + wx0 * wy1 * v01 + wx1 * wy1 * v11);
    }
    g_out[(size_t)m * DMODEL + h * 32 + lane] = acc;
}

// ---------------- masked camera combine with count normalization ----------------
__global__ void k_combine() {
    int i = blockIdx.x * blockDim.x + threadIdx.x;
    if (i >= NQ * DMODEL) return;
    const int qi = i >> 8;     // / DMODEL
    const int c  = i & 255;
    float s = 0.0f, cnt = 0.0f;
    #pragma unroll
    for (int cam = 0; cam < NCAM; cam++) {
        const float v = g_valid[cam * NQ + qi];
        cnt += v;
        s += v * g_qa[((size_t)(cam * NQ + qi)) * DMODEL + c];
    }
    g_slots[i] = s / fmaxf(cnt, 1.0f);
}

// ---------------- launch ----------------
extern "C" void kernel_launch(void* const* d_in, const int* in_sizes, int n_in,
                              void* d_out, int out_size)
{
    const float* queries   = (const float*)d_in[0];
    const float* pos_emb   = (const float*)d_in[1];
    const float* lvl_emb   = (const float*)d_in[2];
    const float* cam_emb   = (const float*)d_in[3];
    const float* features  = (const float*)d_in[4];
    const float* refpts    = (const float*)d_in[5];
    const float* W_off     = (const float*)d_in[6];
    const float* b_off     = (const float*)d_in[7];
    const float* W_attn    = (const float*)d_in[8];
    const float* b_attn    = (const float*)d_in[9];
    const float* W_val     = (const float*)d_in[10];
    const float* b_val     = (const float*)d_in[11];
    const float* W_ao      = (const float*)d_in[12];
    const float* b_ao      = (const float*)d_in[13];
    const float* W_out     = (const float*)d_in[14];
    const float* b_out     = (const float*)d_in[15];
    const int*   bev_mask  = (const int*)d_in[16];
    float* out = (float*)d_out;

    // 1. qp = queries + pos_emb
    k_qp<<<(BNQ * DMODEL + 255) / 256, 256>>>(queries, pos_emb);

    // 2. src = transpose(features) + lvl_emb + cam_emb
    {
        dim3 g(FHW / 32, DMODEL / 32, NCAM), b(32, 8);
        k_src<<<g, b>>>(features, lvl_emb, cam_emb);
    }

    // 3. value = src @ W_val^T + b_val   (padded M; pad rows are zeros)
    k_gemm_value<<<dim3(DMODEL / 64, MVP / 128), 256>>>(W_val, b_val);

    // 4. off = qp @ W_off^T + b_off   (128 outputs)
    k_gemm_off<<<dim3((NHEADS * NPOINTS * 2) / 64, BNQ / 128), 256>>>(W_off, b_off);

    // 5. attn logits = qp @ W_attn^T + b_attn   (64 outputs)
    k_gemm_attn<<<dim3((NHEADS * NPOINTS) / 64, BNQ / 128), 256>>>(W_attn, b_attn);

    // 6. per (cam,q) validity from bev_mask
    k_valid<<<(NCAM * NQ + 255) / 256, 256>>>(bev_mask);

    // 7. softmax + bilinear sampling + weighted accumulate
    k_sample<<<(BNQ * NHEADS * 32) / 256, 256>>>(refpts);

    // 8. qa = out @ W_attn_out^T + b_attn_out
    k_gemm_attnout<<<dim3(DMODEL / 64, BNQ / 128), 256>>>(W_ao, b_ao);

    // 9. masked camera combine
    k_combine<<<(NQ * DMODEL + 255) / 256, 256>>>();

    // 10. final = slots @ W_out^T + b_out  -> d_out
    k_gemm_final<<<dim3(DMODEL / 64, NQ / 128), 256>>>(W_out, b_out, out);
}

// round 5
// speedup vs baseline: 1.0177x; 1.0177x over previous
#include <cuda_runtime.h>
#include <math.h>

// ---------------- problem constants ----------------
#define NHEADS 8
#define NPOINTS 8
#define NDZ 4
#define DMODEL 256
#define NCAM 6
#define NQ 4096
#define FH 56
#define FW 100
#define FHW (FH*FW)          // 5600
#define BNQ (NCAM*NQ)        // 24576 rows of (cam,query)
#define MV  (NCAM*FHW)       // 33600 rows of (cam,pixel)
#define MVP 33664            // MV padded to multiple of 128

// ---------------- scratch (device globals; no allocation) ----------------
__device__ float g_value[MVP*DMODEL];          // value projection (pad rows junk, never read)
__device__ float g_off  [BNQ*NHEADS*NPOINTS*2];// raw sampling offsets (pixels)
__device__ float g_attn [BNQ*NHEADS*NPOINTS];  // attention logits
__device__ float g_out  [BNQ*DMODEL];          // sampled+weighted output
__device__ float g_qa   [BNQ*DMODEL];          // attn-out projection
__device__ float g_slots[NQ*DMODEL];           // masked camera-combine
__device__ float g_valid[NCAM*NQ];             // per (cam,q) validity

// ============================================================================
// GEMM variant A: BM=128, BN=64, BK=16, 8x4 microtile (for narrow-N / small-M)
// C[M,N] = A[M,K] @ B[N,K]^T + bias. M%128==0, N%64==0, K%16==0.
// ============================================================================
template<int N, int K>
__device__ __forceinline__ void sgemm_bt64(const float* __restrict__ A,
                                           const float* __restrict__ B,
                                           const float* __restrict__ bias,
                                           float* __restrict__ C)
{
    constexpr int BM = 128, BN = 64, BK = 16;
    __shared__ float sA[2][BK][BM];
    __shared__ float sB[2][BK][BN];

    const int t  = threadIdx.x;
    const int tx = t & 15;               // cols tx*4
    const int ty = t >> 4;               // rows ty*8
    const int m0 = blockIdx.y * BM;
    const int n0 = blockIdx.x * BN;

    const int alr = t >> 1;              // A row 0..127
    const int alk = (t & 1) * 8;         // 0 or 8
    const int blr = t >> 2;              // B row 0..63
    const int blk = (t & 3) * 4;

    const float* Ap = A + (size_t)(m0 + alr) * K + alk;
    const float* Bp = B + (size_t)(n0 + blr) * K + blk;

    float4 a0 = *(const float4*)(Ap);
    float4 a1 = *(const float4*)(Ap + 4);
    float4 b0 = *(const float4*)(Bp);

    float acc[8][4] = {};
    int buf = 0;

    for (int k0 = 0; k0 < K; k0 += BK) {
        sA[buf][alk+0][alr] = a0.x; sA[buf][alk+1][alr] = a0.y;
        sA[buf][alk+2][alr] = a0.z; sA[buf][alk+3][alr] = a0.w;
        sA[buf][alk+4][alr] = a1.x; sA[buf][alk+5][alr] = a1.y;
        sA[buf][alk+6][alr] = a1.z; sA[buf][alk+7][alr] = a1.w;
        sB[buf][blk+0][blr] = b0.x; sB[buf][blk+1][blr] = b0.y;
        sB[buf][blk+2][blr] = b0.z; sB[buf][blk+3][blr] = b0.w;
        __syncthreads();

        if (k0 + BK < K) {
            a0 = *(const float4*)(Ap + k0 + BK);
            a1 = *(const float4*)(Ap + k0 + BK + 4);
            b0 = *(const float4*)(Bp + k0 + BK);
        }

        #pragma unroll
        for (int kk = 0; kk < BK; kk++) {
            float4 ra0 = *(const float4*)(&sA[buf][kk][ty * 8]);
            float4 ra1 = *(const float4*)(&sA[buf][kk][ty * 8 + 4]);
            float4 rb  = *(const float4*)(&sB[buf][kk][tx * 4]);
            float av[8] = {ra0.x, ra0.y, ra0.z, ra0.w, ra1.x, ra1.y, ra1.z, ra1.w};
            float bv[4] = {rb.x, rb.y, rb.z, rb.w};
            #pragma unroll
            for (int i = 0; i < 8; i++)
                #pragma unroll
                for (int j = 0; j < 4; j++)
                    acc[i][j] += av[i] * bv[j];
        }
        buf ^= 1;
    }

    float4 bb = *(const float4*)(bias + n0 + tx * 4);
    #pragma unroll
    for (int i = 0; i < 8; i++) {
        float4 o;
        o.x = acc[i][0] + bb.x; o.y = acc[i][1] + bb.y;
        o.z = acc[i][2] + bb.z; o.w = acc[i][3] + bb.w;
        *(float4*)(C + (size_t)(m0 + ty * 8 + i) * N + n0 + tx * 4) = o;
    }
}

// ============================================================================
// Fused off+attn GEMM: A = queries + pos_emb computed on the fly.
// N logically 192: block x = 0,1 -> W_off (128 cols), 2 -> W_attn (64 cols).
// ============================================================================
__global__ __launch_bounds__(256) void k_gemm_offattn(
    const float* __restrict__ queries, const float* __restrict__ pos,
    const float* __restrict__ Woff, const float* __restrict__ boff,
    const float* __restrict__ Watt, const float* __restrict__ batt)
{
    constexpr int BM = 128, BN = 64, BK = 16, K = DMODEL;
    __shared__ float sA[2][BK][BM];
    __shared__ float sB[2][BK][BN];

    const int t  = threadIdx.x;
    const int tx = t & 15;
    const int ty = t >> 4;
    const int m0 = blockIdx.y * BM;
    const int n0 = blockIdx.x * BN;             // 0,64,128
    const bool is_off = (n0 < 128);
    const float* B    = is_off ? Woff : Watt;
    const float* bias = is_off ? boff : batt;
    const int nb      = is_off ? n0 : 0;        // row base within B

    const int alr = t >> 1;
    const int alk = (t & 1) * 8;
    const int blr = t >> 2;
    const int blk = (t & 3) * 4;

    const int gm = m0 + alr;
    const float* Ap = queries + (size_t)gm * K + alk;
    const float* Pp = pos + (size_t)(gm & (NQ - 1)) * K + alk;   // pos broadcast over cams
    const float* Bp = B + (size_t)(nb + blr) * K + blk;

    float4 a0 = *(const float4*)(Ap);
    float4 a1 = *(const float4*)(Ap + 4);
    float4 p0 = *(const float4*)(Pp);
    float4 p1 = *(const float4*)(Pp + 4);
    float4 b0 = *(const float4*)(Bp);

    float acc[8][4] = {};
    int buf = 0;

    for (int k0 = 0; k0 < K; k0 += BK) {
        sA[buf][alk+0][alr] = a0.x + p0.x; sA[buf][alk+1][alr] = a0.y + p0.y;
        sA[buf][alk+2][alr] = a0.z + p0.z; sA[buf][alk+3][alr] = a0.w + p0.w;
        sA[buf][alk+4][alr] = a1.x + p1.x; sA[buf][alk+5][alr] = a1.y + p1.y;
        sA[buf][alk+6][alr] = a1.z + p1.z; sA[buf][alk+7][alr] = a1.w + p1.w;
        sB[buf][blk+0][blr] = b0.x; sB[buf][blk+1][blr] = b0.y;
        sB[buf][blk+2][blr] = b0.z; sB[buf][blk+3][blr] = b0.w;
        __syncthreads();

        if (k0 + BK < K) {
            a0 = *(const float4*)(Ap + k0 + BK);
            a1 = *(const float4*)(Ap + k0 + BK + 4);
            p0 = *(const float4*)(Pp + k0 + BK);
            p1 = *(const float4*)(Pp + k0 + BK + 4);
            b0 = *(const float4*)(Bp + k0 + BK);
        }

        #pragma unroll
        for (int kk = 0; kk < BK; kk++) {
            float4 ra0 = *(const float4*)(&sA[buf][kk][ty * 8]);
            float4 ra1 = *(const float4*)(&sA[buf][kk][ty * 8 + 4]);
            float4 rb  = *(const float4*)(&sB[buf][kk][tx * 4]);
            float av[8] = {ra0.x, ra0.y, ra0.z, ra0.w, ra1.x, ra1.y, ra1.z, ra1.w};
            float bv[4] = {rb.x, rb.y, rb.z, rb.w};
            #pragma unroll
            for (int i = 0; i < 8; i++)
                #pragma unroll
                for (int j = 0; j < 4; j++)
                    acc[i][j] += av[i] * bv[j];
        }
        buf ^= 1;
    }

    float4 bb = *(const float4*)(bias + nb + tx * 4);
    #pragma unroll
    for (int i = 0; i < 8; i++) {
        float4 o;
        o.x = acc[i][0] + bb.x; o.y = acc[i][1] + bb.y;
        o.z = acc[i][2] + bb.z; o.w = acc[i][3] + bb.w;
        const int row = m0 + ty * 8 + i;
        if (is_off)
            *(float4*)(g_off  + (size_t)row * 128 + n0 + tx * 4) = o;
        else
            *(float4*)(g_attn + (size_t)row * 64 + tx * 4) = o;
    }
}

// ============================================================================
// Value GEMM: BM=128, BN=128, BK=16, 8x8 microtile.
// A tile read straight from features (cam,c,pix) + lvl/cam embeddings fused.
// ============================================================================
__global__ __launch_bounds__(256) void k_gemm_value(
    const float* __restrict__ feat, const float* __restrict__ lvl,
    const float* __restrict__ came, const float* __restrict__ W,
    const float* __restrict__ bias)
{
    constexpr int BM = 128, BN = 128, BK = 16, K = DMODEL;
    __shared__ float sA[2][BK][BM];
    __shared__ float sB[2][BK][BM];

    const int t  = threadIdx.x;
    const int tx = t & 15;               // cols tx*8
    const int ty = t >> 4;               // rows ty*8
    const int m0 = blockIdx.y * BM;
    const int n0 = blockIdx.x * BN;

    // A loader: tp = pixel-row in tile, tc selects channel half (8 ch each)
    const int tp = t & 127;
    const int tc = t >> 7;               // 0 or 1
    const int gm = m0 + tp;
    const bool arow_ok = (gm < MV);
    int cam = 0, p = 0;
    if (arow_ok) { cam = gm / FHW; p = gm - cam * FHW; }
    const float* fb = feat + (size_t)cam * (DMODEL * FHW) + p;
    const float* eb_l = lvl;                          // [DMODEL]
    const float* eb_c = came + cam * DMODEL;          // [DMODEL]

    // B loader
    const int blr = t >> 1;
    const int blk = (t & 1) * 8;
    const float* Bp = W + (size_t)(n0 + blr) * K + blk;

    float a_pre[8];
    #pragma unroll
    for (int j = 0; j < 8; j++) {
        const int c = tc * 8 + j;
        a_pre[j] = arow_ok ? (fb[(size_t)c * FHW] + eb_l[c] + eb_c[c]) : 0.0f;
    }
    float4 b0 = *(const float4*)(Bp);
    float4 b1 = *(const float4*)(Bp + 4);

    float acc[8][8] = {};
    int buf = 0;

    for (int k0 = 0; k0 < K; k0 += BK) {
        #pragma unroll
        for (int j = 0; j < 8; j++)
            sA[buf][tc * 8 + j][tp] = a_pre[j];
        sB[buf][blk+0][blr] = b0.x; sB[buf][blk+1][blr] = b0.y;
        sB[buf][blk+2][blr] = b0.z; sB[buf][blk+3][blr] = b0.w;
        sB[buf][blk+4][blr] = b1.x; sB[buf][blk+5][blr] = b1.y;
        sB[buf][blk+6][blr] = b1.z; sB[buf][blk+7][blr] = b1.w;
        __syncthreads();

        if (k0 + BK < K) {
            const int kn = k0 + BK;
            #pragma unroll
            for (int j = 0; j < 8; j++) {
                const int c = kn + tc * 8 + j;
                a_pre[j] = arow_ok ? (fb[(size_t)c * FHW] + eb_l[c] + eb_c[c]) : 0.0f;
            }
            b0 = *(const float4*)(Bp + kn);
            b1 = *(const float4*)(Bp + kn + 4);
        }

        #pragma unroll
        for (int kk = 0; kk < BK; kk++) {
            float4 ra0 = *(const float4*)(&sA[buf][kk][ty * 8]);
            float4 ra1 = *(const float4*)(&sA[buf][kk][ty * 8 + 4]);
            float4 rb0 = *(const float4*)(&sB[buf][kk][tx * 8]);
            float4 rb1 = *(const float4*)(&sB[buf][kk][tx * 8 + 4]);
            float av[8] = {ra0.x, ra0.y, ra0.z, ra0.w, ra1.x, ra1.y, ra1.z, ra1.w};
            float bv[8] = {rb0.x, rb0.y, rb0.z, rb0.w, rb1.x, rb1.y, rb1.z, rb1.w};
            #pragma unroll
            for (int i = 0; i < 8; i++)
                #pragma unroll
                for (int j = 0; j < 8; j++)
                    acc[i][j] += av[i] * bv[j];
        }
        buf ^= 1;
    }

    float4 bb0 = *(const float4*)(bias + n0 + tx * 8);
    float4 bb1 = *(const float4*)(bias + n0 + tx * 8 + 4);
    #pragma unroll
    for (int i = 0; i < 8; i++) {
        float* Crow = g_value + (size_t)(m0 + ty * 8 + i) * DMODEL + n0 + tx * 8;
        float4 o0, o1;
        o0.x = acc[i][0] + bb0.x; o0.y = acc[i][1] + bb0.y;
        o0.z = acc[i][2] + bb0.z; o0.w = acc[i][3] + bb0.w;
        o1.x = acc[i][4] + bb1.x; o1.y = acc[i][5] + bb1.y;
        o1.z = acc[i][6] + bb1.z; o1.w = acc[i][7] + bb1.w;
        *(float4*)(Crow) = o0;
        *(float4*)(Crow + 4) = o1;
    }
}

// ============================================================================
// attn_out GEMM: BM=128, BN=128, BK=16, 8x8 microtile, standard A (g_out).
// ============================================================================
__global__ __launch_bounds__(256) void k_gemm_attnout(
    const float* __restrict__ W, const float* __restrict__ bias)
{
    constexpr int BM = 128, BN = 128, BK = 16, K = DMODEL;
    __shared__ float sA[2][BK][BM];
    __shared__ float sB[2][BK][BM];

    const int t  = threadIdx.x;
    const int tx = t & 15;
    const int ty = t >> 4;
    const int m0 = blockIdx.y * BM;
    const int n0 = blockIdx.x * BN;

    const int alr = t >> 1;
    const int alk = (t & 1) * 8;
    const float* Ap = g_out + (size_t)(m0 + alr) * K + alk;
    const float* Bp = W + (size_t)(n0 + alr) * K + alk;

    float4 a0 = *(const float4*)(Ap);
    float4 a1 = *(const float4*)(Ap + 4);
    float4 b0 = *(const float4*)(Bp);
    float4 b1 = *(const float4*)(Bp + 4);

    float acc[8][8] = {};
    int buf = 0;

    for (int k0 = 0; k0 < K; k0 += BK) {
        sA[buf][alk+0][alr] = a0.x; sA[buf][alk+1][alr] = a0.y;
        sA[buf][alk+2][alr] = a0.z; sA[buf][alk+3][alr] = a0.w;
        sA[buf][alk+4][alr] = a1.x; sA[buf][alk+5][alr] = a1.y;
        sA[buf][alk+6][alr] = a1.z; sA[buf][alk+7][alr] = a1.w;
        sB[buf][alk+0][alr] = b0.x; sB[buf][alk+1][alr] = b0.y;
        sB[buf][alk+2][alr] = b0.z; sB[buf][alk+3][alr] = b0.w;
        sB[buf][alk+4][alr] = b1.x; sB[buf][alk+5][alr] = b1.y;
        sB[buf][alk+6][alr] = b1.z; sB[buf][alk+7][alr] = b1.w;
        __syncthreads();

        if (k0 + BK < K) {
            a0 = *(const float4*)(Ap + k0 + BK);
            a1 = *(const float4*)(Ap + k0 + BK + 4);
            b0 = *(const float4*)(Bp + k0 + BK);
            b1 = *(const float4*)(Bp + k0 + BK + 4);
        }

        #pragma unroll
        for (int kk = 0; kk < BK; kk++) {
            float4 ra0 = *(const float4*)(&sA[buf][kk][ty * 8]);
            float4 ra1 = *(const float4*)(&sA[buf][kk][ty * 8 + 4]);
            float4 rb0 = *(const float4*)(&sB[buf][kk][tx * 8]);
            float4 rb1 = *(const float4*)(&sB[buf][kk][tx * 8 + 4]);
            float av[8] = {ra0.x, ra0.y, ra0.z, ra0.w, ra1.x, ra1.y, ra1.z, ra1.w};
            float bv[8] = {rb0.x, rb0.y, rb0.z, rb0.w, rb1.x, rb1.y, rb1.z, rb1.w};
            #pragma unroll
            for (int i = 0; i < 8; i++)
                #pragma unroll
                for (int j = 0; j < 8; j++)
                    acc[i][j] += av[i] * bv[j];
        }
        buf ^= 1;
    }

    float4 bb0 = *(const float4*)(bias + n0 + tx * 8);
    float4 bb1 = *(const float4*)(bias + n0 + tx * 8 + 4);
    #pragma unroll
    for (int i = 0; i < 8; i++) {
        float* Crow = g_qa + (size_t)(m0 + ty * 8 + i) * DMODEL + n0 + tx * 8;
        float4 o0, o1;
        o0.x = acc[i][0] + bb0.x; o0.y = acc[i][1] + bb0.y;
        o0.z = acc[i][2] + bb0.z; o0.w = acc[i][3] + bb0.w;
        o1.x = acc[i][4] + bb1.x; o1.y = acc[i][5] + bb1.y;
        o1.z = acc[i][6] + bb1.z; o1.w = acc[i][7] + bb1.w;
        *(float4*)(Crow) = o0;
        *(float4*)(Crow + 4) = o1;
    }
}

// final = slots @ W_out^T + b_out (small M; use 128x64 variant)
__global__ __launch_bounds__(256) void k_gemm_final(const float* W, const float* b, float* C) {
    sgemm_bt64<DMODEL, DMODEL>(g_slots, W, b, C);
}

// ---------------- validity: any over z of bev_mask[0,cam,q,z,0] ----------------
__global__ void k_valid(const int* __restrict__ mask) {
    int i = blockIdx.x * blockDim.x + threadIdx.x;
    if (i >= NCAM * NQ) return;
    const int* mp = mask + (size_t)i * (NDZ * 2);
    g_valid[i] = (mp[0] | mp[2] | mp[4] | mp[6]) ? 1.0f : 0.0f;
}

// ---------------- sampling: softmax + bilinear gather + weighted sum ----------------
__global__ __launch_bounds__(256) void k_sample(const float* __restrict__ refpts) {
    const int gwarp = (blockIdx.x * blockDim.x + threadIdx.x) >> 5;
    const int lane  = threadIdx.x & 31;
    const int h = gwarp & 7;
    const int m = gwarp >> 3;              // 0..BNQ-1
    if (m >= BNQ) return;
    const int cam = m >> 12;

    const float* lg = g_attn + (size_t)m * (NHEADS * NPOINTS) + h * NPOINTS;
    float l[NPOINTS];
    float mx = -1e30f;
    #pragma unroll
    for (int p = 0; p < NPOINTS; p++) { l[p] = lg[p]; mx = fmaxf(mx, l[p]); }
    float ssum = 0.0f;
    #pragma unroll
    for (int p = 0; p < NPOINTS; p++) { l[p] = __expf(l[p] - mx); ssum += l[p]; }
    const float inv = 1.0f / ssum;

    const float* offp = g_off + (size_t)m * (NHEADS * NPOINTS * 2) + h * (NPOINTS * 2);
    const float* rp   = refpts + (size_t)m * (NDZ * 2);
    const float* vb   = g_value + ((size_t)cam * FHW) * DMODEL + h * 32 + lane;

    float acc = 0.0f;
    #pragma unroll
    for (int p = 0; p < NPOINTS; p++) {
        const float wq = l[p] * inv;
        const int z = p & 3;
        const float x = rp[z * 2 + 0] * (float)FW + offp[p * 2 + 0] - 0.5f;
        const float y = rp[z * 2 + 1] * (float)FH + offp[p * 2 + 1] - 0.5f;
        const float x0f = floorf(x), y0f = floorf(y);
        const int x0 = (int)x0f, y0 = (int)y0f;
        const int x1 = x0 + 1,  y1 = y0 + 1;
        const float wx1 = x - x0f, wx0 = 1.0f - wx1;
        const float wy1 = y - y0f, wy0 = 1.0f - wy1;
        const bool vx0 = (x0 >= 0) & (x0 < FW);
        const bool vx1 = (x1 >= 0) & (x1 < FW);
        const bool vy0 = (y0 >= 0) & (y0 < FH);
        const bool vy1 = (y1 >= 0) & (y1 < FH);
        float v00 = (vx0 & vy0) ? vb[(size_t)(y0 * FW + x0) * DMODEL] : 0.0f;
        float v10 = (vx1 & vy0) ? vb[(size_t)(y0 * FW + x1) * DMODEL] : 0.0f;
        float v01 = (vx0 & vy1) ? vb[(size_t)(y1 * FW + x0) * DMODEL] : 0.0f;
        float v11 = (vx1 & vy1) ? vb[(size_t)(y1 * FW + x1) * DMODEL] : 0.0f;
        acc += wq * (wx0 * wy0 * v00 + wx1 * wy0 * v10 + wx0 * wy1 * v01 + wx1 * wy1 * v11);
    }
    g_out[(size_t)m * DMODEL + h * 32 + lane] = acc;
}

// ---------------- masked camera combine with count normalization ----------------
__global__ void k_combine() {
    int i = blockIdx.x * blockDim.x + threadIdx.x;
    if (i >= NQ * DMODEL) return;
    const int qi = i >> 8;
    const int c  = i & 255;
    float s = 0.0f, cnt = 0.0f;
    #pragma unroll
    for (int cam = 0; cam < NCAM; cam++) {
        const float v = g_valid[cam * NQ + qi];
        cnt += v;
        s += v * g_qa[((size_t)(cam * NQ + qi)) * DMODEL + c];
    }
    g_slots[i] = s / fmaxf(cnt, 1.0f);
}

// ---------------- launch ----------------
extern "C" void kernel_launch(void* const* d_in, const int* in_sizes, int n_in,
                              void* d_out, int out_size)
{
    const float* queries   = (const float*)d_in[0];
    const float* pos_emb   = (const float*)d_in[1];
    const float* lvl_emb   = (const float*)d_in[2];
    const float* cam_emb   = (const float*)d_in[3];
    const float* features  = (const float*)d_in[4];
    const float* refpts    = (const float*)d_in[5];
    const float* W_off     = (const float*)d_in[6];
    const float* b_off     = (const float*)d_in[7];
    const float* W_attn    = (const float*)d_in[8];
    const float* b_attn    = (const float*)d_in[9];
    const float* W_val     = (const float*)d_in[10];
    const float* b_val     = (const float*)d_in[11];
    const float* W_ao      = (const float*)d_in[12];
    const float* b_ao      = (const float*)d_in[13];
    const float* W_out     = (const float*)d_in[14];
    const float* b_out     = (const float*)d_in[15];
    const int*   bev_mask  = (const int*)d_in[16];
    float* out = (float*)d_out;

    // 1. off+attn projections, qp fused into A load  (grid x: 2 off tiles + 1 attn tile)
    k_gemm_offattn<<<dim3(3, BNQ / 128), 256>>>(queries, pos_emb,
                                                W_off, b_off, W_attn, b_attn);

    // 2. value projection, transpose+embeddings fused into A load
    k_gemm_value<<<dim3(DMODEL / 128, MVP / 128), 256>>>(features, lvl_emb, cam_emb,
                                                         W_val, b_val);

    // 3. per (cam,q) validity
    k_valid<<<(NCAM * NQ + 255) / 256, 256>>>(bev_mask);

    // 4. softmax + bilinear sampling + weighted accumulate
    k_sample<<<(BNQ * NHEADS * 32) / 256, 256>>>(refpts);

    // 5. qa = out @ W_attn_out^T + b_attn_out
    k_gemm_attnout<<<dim3(DMODEL / 128, BNQ / 128), 256>>>(W_ao, b_ao);

    // 6. masked camera combine
    k_combine<<<(NQ * DMODEL + 255) / 256, 256>>>();

    // 7. final = slots @ W_out^T + b_out -> d_out
    k_gemm_final<<<dim3(DMODEL / 64, NQ / 128), 256>>>(W_out, b_out, out);
}